// round 15
// baseline (speedup 1.0000x reference)
#include <cuda_runtime.h>
#include <math.h>

#define T_STEPS 1024
#define NB 128
#define FD 128
#define HD 128

// Scratch: 8 precomputed floats per (b,t):
//  [0:4) = x_t @ W_in_x^T + b_in   (x-part of y)
//  [4:8) = vqc(x_t @ W_x^T + b_x, vqc_w[2])  (fully h-independent)
__device__ float g_xpre[NB * T_STEPS * 8];

typedef unsigned long long u64;

__device__ __forceinline__ u64 pack2(float lo, float hi) {
    u64 r;
    asm("mov.b64 %0, {%1, %2};" : "=l"(r) : "f"(lo), "f"(hi));
    return r;
}
__device__ __forceinline__ void unpack2(u64 v, float& lo, float& hi) {
    asm("mov.b64 {%0, %1}, %2;" : "=f"(lo), "=f"(hi) : "l"(v));
}
__device__ __forceinline__ u64 fma2(u64 a, u64 b, u64 c) {
    u64 r;
    asm("fma.rn.f32x2 %0, %1, %2, %3;" : "=l"(r) : "l"(a), "l"(b), "l"(c));
    return r;
}
__device__ __forceinline__ u64 add2(u64 a, u64 b) {
    u64 r;
    asm("add.rn.f32x2 %0, %1, %2;" : "=l"(r) : "l"(a), "l"(b));
    return r;
}
__device__ __forceinline__ float ex2f(float x) {
    float r;
    asm("ex2.approx.f32 %0, %1;" : "=f"(r) : "f"(x));
    return r;
}
__device__ __forceinline__ float rcpf(float x) {
    float r;
    asm("rcp.approx.f32 %0, %1;" : "=f"(r) : "f"(x));
    return r;
}

// ---------------------------------------------------------------------------
// Pre-pass (R14 version — FROZEN): 16 rows/warp, chunked double-buffering,
// 9-shuffle value-splitting butterfly per row.
// ---------------------------------------------------------------------------
#define PP_WARPS 8192

__global__ void __launch_bounds__(256) qgru_prepass(
    const float* __restrict__ x,
    const float* __restrict__ W_in, const float* __restrict__ b_in,
    const float* __restrict__ W_x,  const float* __restrict__ b_x,
    const float* __restrict__ vqc_w)
{
    const int lane = threadIdx.x & 31;
    const int gw   = (blockIdx.x * blockDim.x + threadIdx.x) >> 5;  // 0..8191
    const int k    = lane >> 2;
    const int q    = lane & 3;

    u64 wt0[8], wt1[8];
#pragma unroll
    for (int kk = 0; kk < 8; kk++) {
        const float* row = (kk < 4) ? (W_in + kk * (HD + FD) + HD)
                                    : (W_x + (kk - 4) * FD);
        float4 wv = *reinterpret_cast<const float4*>(row + 4 * lane);
        wt0[kk] = pack2(wv.x, wv.y);
        wt1[kk] = pack2(wv.z, wv.w);
    }
    const float bias_l = (k < 4) ? b_in[k]
                                 : (b_x[k - 4] + vqc_w[8 + (k - 4)]);

    const int hi = (lane >> 4) & 1;
    const int h3 = (lane >> 3) & 1;
    const int h2 = (lane >> 2) & 1;

    const float* xr = x + 4 * lane;

    auto process = [&](float4 xv, int row) {
        u64 x01 = pack2(xv.x, xv.y);
        u64 x23 = pack2(xv.z, xv.w);

        float v[8];
#pragma unroll
        for (int kk = 0; kk < 8; kk++) {
            u64 acc = fma2(x01, wt0[kk], fma2(x23, wt1[kk], 0ull));
            float lo, hiF;
            unpack2(acc, lo, hiF);
            v[kk] = lo + hiF;
        }

        float u4_0, u4_1, u4_2, u4_3;
        {
            float s0 = hi ? v[0] : v[4];
            float s1 = hi ? v[1] : v[5];
            float s2 = hi ? v[2] : v[6];
            float s3 = hi ? v[3] : v[7];
            float r0 = __shfl_xor_sync(0xffffffffu, s0, 16);
            float r1 = __shfl_xor_sync(0xffffffffu, s1, 16);
            float r2 = __shfl_xor_sync(0xffffffffu, s2, 16);
            float r3 = __shfl_xor_sync(0xffffffffu, s3, 16);
            u4_0 = (hi ? v[4] : v[0]) + r0;
            u4_1 = (hi ? v[5] : v[1]) + r1;
            u4_2 = (hi ? v[6] : v[2]) + r2;
            u4_3 = (hi ? v[7] : v[3]) + r3;
        }
        float u2_0, u2_1;
        {
            float s0 = h3 ? u4_0 : u4_2;
            float s1 = h3 ? u4_1 : u4_3;
            float r0 = __shfl_xor_sync(0xffffffffu, s0, 8);
            float r1 = __shfl_xor_sync(0xffffffffu, s1, 8);
            u2_0 = (h3 ? u4_2 : u4_0) + r0;
            u2_1 = (h3 ? u4_3 : u4_1) + r1;
        }
        float s;
        {
            float s0 = h2 ? u2_0 : u2_1;
            float r0 = __shfl_xor_sync(0xffffffffu, s0, 4);
            s = (h2 ? u2_1 : u2_0) + r0;
        }
        s += __shfl_xor_sync(0xffffffffu, s, 2);
        s += __shfl_xor_sync(0xffffffffu, s, 1);

        float val = s + bias_l;
        float cv  = __cosf(val);
        float c0 = __shfl_sync(0xffffffffu, cv, 16);
        float c1 = __shfl_sync(0xffffffffu, cv, 20);
        float c2 = __shfl_sync(0xffffffffu, cv, 24);
        float c3 = __shfl_sync(0xffffffffu, cv, 28);

        if (q == 0) {
            float sval;
            if (k < 4) {
                sval = val;
            } else {
                float z1 = c0 * c1, z2 = z1 * c2;
                sval = (k == 4) ? c1 * c2 * c3
                     : (k == 5) ? z1
                     : (k == 6) ? z2
                                : z2 * c3;
            }
            g_xpre[(size_t)row * 8 + k] = sval;
        }
    };

    float4 c0v = *reinterpret_cast<const float4*>(xr + (size_t)(gw + 0 * PP_WARPS) * FD);
    float4 c1v = *reinterpret_cast<const float4*>(xr + (size_t)(gw + 1 * PP_WARPS) * FD);
    float4 c2v = *reinterpret_cast<const float4*>(xr + (size_t)(gw + 2 * PP_WARPS) * FD);
    float4 c3v = *reinterpret_cast<const float4*>(xr + (size_t)(gw + 3 * PP_WARPS) * FD);

#pragma unroll
    for (int c = 0; c < 4; c++) {
        float4 n0, n1, n2, n3;
        if (c < 3) {
            const int nb = (c + 1) * 4;
            n0 = *reinterpret_cast<const float4*>(xr + (size_t)(gw + (nb + 0) * PP_WARPS) * FD);
            n1 = *reinterpret_cast<const float4*>(xr + (size_t)(gw + (nb + 1) * PP_WARPS) * FD);
            n2 = *reinterpret_cast<const float4*>(xr + (size_t)(gw + (nb + 2) * PP_WARPS) * FD);
            n3 = *reinterpret_cast<const float4*>(xr + (size_t)(gw + (nb + 3) * PP_WARPS) * FD);
        }
        const int rb = c * 4;
        process(c0v, gw + (rb + 0) * PP_WARPS);
        process(c1v, gw + (rb + 1) * PP_WARPS);
        process(c2v, gw + (rb + 2) * PP_WARPS);
        process(c3v, gw + (rb + 3) * PP_WARPS);
        c0v = n0; c1v = n1; c2v = n2; c3v = n3;
    }
}

// ---------------------------------------------------------------------------
// Sequential recurrence: TWO independent batch rows per 256-thread CTA.
// Warps 0-3 = row A, warps 4-7 = row B; each row group syncs on its OWN
// named barrier (bar.sync 1,128 / 2,128) so the rows never couple — each
// SMSP holds 2 warps with independent chains, filling the ~70% idle issue
// slots of the 1-row version. Per-row step body = R13 seq (proven), with
// only indexing + barrier changed. Dynamic smem: 2x32KB xs + psum.
// ---------------------------------------------------------------------------
__global__ void __launch_bounds__(256, 1) qgru_seq(
    const float* __restrict__ W_in, const float* __restrict__ W_h,
    const float* __restrict__ b_h,
    const float* __restrict__ W_out, const float* __restrict__ b_out,
    const float* __restrict__ vqc_w,
    float* __restrict__ out)
{
    extern __shared__ __align__(16) float smem[];

    const int j    = threadIdx.x & 127;   // within-row thread id
    const int row  = threadIdx.x >> 7;    // 0 or 1
    const int b    = blockIdx.x * 2 + row;
    const int lane = threadIdx.x & 31;
    const int w    = (threadIdx.x >> 5) & 3;  // warp within row group
    const int k    = lane >> 2;   // owned sum index after 3-round butterfly
    const int q    = lane & 3;    // partial index this lane holds

    float* xs   = smem + (size_t)row * (T_STEPS * 8);           // 32 KB each
    float* psum = smem + 2 * (T_STEPS * 8) + row * (2 * 8 * 20); // [buf][8*20]

    // ---- stage this row's xpre into smem (128 threads per row)
    {
        const float4* src = reinterpret_cast<const float4*>(
            g_xpre + (size_t)b * T_STEPS * 8);
        float4* dst = reinterpret_cast<float4*>(xs);
        float4 tmp[16];
#pragma unroll
        for (int i = 0; i < 16; i++) tmp[i] = src[j + 128 * i];
#pragma unroll
        for (int i = 0; i < 16; i++) dst[j + 128 * i] = tmp[i];
    }

    // ---- dot weights: wk[kk] = row_kk[j]  (thread j's h column)
    float wk[8];
#pragma unroll
    for (int kk = 0; kk < 8; kk++) {
        const float* wrow = (kk < 4) ? (W_in + kk * (HD + FD))
                                     : (W_h + (kk - 4) * HD);
        wk[kk] = wrow[j];
    }

    // W_out prescaled: RZ by log2e (exp(-o)), HX by 2*log2e (exp(-2u))
    const float L2E = 1.4426950408889634f;
    float woRZ[4], woHX[4];
#pragma unroll
    for (int kk = 0; kk < 4; kk++) {
        float wv = W_out[j * 4 + kk];
        woRZ[kk] = wv * L2E;
        woHX[kk] = wv * (2.0f * L2E);
    }
    const float bof  = b_out[j];
    const float boRZ = bof * L2E;
    const float boHX = bof * (2.0f * L2E);

    // ---- cosine role (loop-invariant): quad k, member q
    float cadd = 0.0f;
    if (k < 4) {
        if (q == 0)      cadd = vqc_w[k];
        else if (q == 1) cadd = vqc_w[4 + k];
    } else if (q == 0) {
        cadd = vqc_w[12 + (k - 4)] + b_h[k - 4];
    }
    const bool use_p = (k < 4);

    const int hi = (lane >> 4) & 1;
    const int h3 = (lane >> 3) & 1;
    const int h2 = (lane >> 2) & 1;

    float hj = 0.0f;                 // h_j lives here; never leaves registers

    // c_last = zeros
    out[(size_t)NB * T_STEPS * HD + (size_t)NB * HD + b * HD + j] = 0.0f;

    float* __restrict__ orow = out + (size_t)b * T_STEPS * HD + j;
    const int pslot = k * 20 + w * 4 + q;   // this lane's psum store index
    const int barid = row + 1;              // named barrier 1 or 2

    __syncthreads();   // xs staged (both rows)

#pragma unroll 1
    for (int t = 0; t < T_STEPS; t++) {
        // ---- pre-barrier: warp-partial dots over this warp's own h slice
        float v[8];
#pragma unroll
        for (int kk = 0; kk < 8; kk++) v[kk] = wk[kk] * hj;

        // 3-round value-splitting butterfly: lane ends with one partial
        // (sum k=lane>>2, over the 8 lanes sharing lane&3)
        float u4_0, u4_1, u4_2, u4_3;
        {
            float s0 = hi ? v[0] : v[4];
            float s1 = hi ? v[1] : v[5];
            float s2 = hi ? v[2] : v[6];
            float s3 = hi ? v[3] : v[7];
            float r0 = __shfl_xor_sync(0xffffffffu, s0, 16);
            float r1 = __shfl_xor_sync(0xffffffffu, s1, 16);
            float r2 = __shfl_xor_sync(0xffffffffu, s2, 16);
            float r3 = __shfl_xor_sync(0xffffffffu, s3, 16);
            u4_0 = (hi ? v[4] : v[0]) + r0;
            u4_1 = (hi ? v[5] : v[1]) + r1;
            u4_2 = (hi ? v[6] : v[2]) + r2;
            u4_3 = (hi ? v[7] : v[3]) + r3;
        }
        float u2_0, u2_1;
        {
            float s0 = h3 ? u4_0 : u4_2;
            float s1 = h3 ? u4_1 : u4_3;
            float r0 = __shfl_xor_sync(0xffffffffu, s0, 8);
            float r1 = __shfl_xor_sync(0xffffffffu, s1, 8);
            u2_0 = (h3 ? u4_2 : u4_0) + r0;
            u2_1 = (h3 ? u4_3 : u4_1) + r1;
        }
        float s;
        {
            float s0 = h2 ? u2_0 : u2_1;
            float r0 = __shfl_xor_sync(0xffffffffu, s0, 4);
            s = (h2 ? u2_1 : u2_0) + r0;
        }

        psum[(t & 1) * 160 + pslot] = s;   // 32 lanes store (conflict-free)

        // psum-independent work overlapping the barrier region
        float4 P1 = *reinterpret_cast<const float4*>(xs + t * 8 + 4);
        float pc  = xs[t * 8 + (k & 3)];
        float o_x = fmaf(P1.x, woHX[0],
                    fmaf(P1.y, woHX[1], fmaf(P1.z, woHX[2],
                    fmaf(P1.w, woHX[3], boHX))));

        // per-row named barrier (rows never couple)
        asm volatile("bar.sync %0, %1;" :: "r"(barid), "r"(128) : "memory");

        // ---- post-barrier: total for owned sum k (16 partials, add2 tree)
        const float* prow = psum + (t & 1) * 160 + k * 20;
        ulonglong2 A = *reinterpret_cast<const ulonglong2*>(prow + 0);
        ulonglong2 B = *reinterpret_cast<const ulonglong2*>(prow + 4);
        ulonglong2 C = *reinterpret_cast<const ulonglong2*>(prow + 8);
        ulonglong2 D = *reinterpret_cast<const ulonglong2*>(prow + 12);
        u64 e0 = add2(A.x, A.y);
        u64 e1 = add2(B.x, B.y);
        u64 e2 = add2(C.x, C.y);
        u64 e3 = add2(D.x, D.y);
        e0 = add2(e0, e1);
        e2 = add2(e2, e3);
        e0 = add2(e0, e2);
        float tlo, thi;
        unpack2(e0, tlo, thi);
        float tot = tlo + thi;

        // one warp-wide cosine; 12 direct shfl.idx broadcasts (no smem)
        float arg = tot + cadd + (use_p ? pc : 0.0f);
        float cv  = __cosf(arg);

        float cr0 = __shfl_sync(0xffffffffu, cv, 0);
        float cr1 = __shfl_sync(0xffffffffu, cv, 4);
        float cr2 = __shfl_sync(0xffffffffu, cv, 8);
        float cr3 = __shfl_sync(0xffffffffu, cv, 12);
        float cz0 = __shfl_sync(0xffffffffu, cv, 1);
        float cz1 = __shfl_sync(0xffffffffu, cv, 5);
        float cz2 = __shfl_sync(0xffffffffu, cv, 9);
        float cz3 = __shfl_sync(0xffffffffu, cv, 13);
        float ch0 = __shfl_sync(0xffffffffu, cv, 16);
        float ch1 = __shfl_sync(0xffffffffu, cv, 20);
        float ch2 = __shfl_sync(0xffffffffu, cv, 24);
        float ch3 = __shfl_sync(0xffffffffu, cv, 28);

        // z-expectations after CNOT ring: (C1C2C3, C0C1, C0C1C2, C0C1C2C3)
        float rm = cr1 * cr2;
        float rA = cr0 * cr1, rB = cr0 * rm;
        float o_r = fmaf(rm * cr3, woRZ[0],
                    fmaf(rA, woRZ[1], fmaf(rB, woRZ[2],
                    fmaf(rB * cr3, woRZ[3], boRZ))));
        float Er = ex2f(-o_r);

        float hm = ch1 * ch2;
        float hA = ch0 * ch1, hB = ch0 * hm;
        float o_h = fmaf(hm * ch3, woHX[0],
                    fmaf(hA, woHX[1], fmaf(hB, woHX[2],
                    fmaf(hB * ch3, woHX[3], boHX))));

        float zm = cz1 * cz2;
        float zA = cz0 * cz1, zB = cz0 * zm;
        float o_z = fmaf(zm * cz3, woRZ[0],
                    fmaf(zA, woRZ[1], fmaf(zB, woRZ[2],
                    fmaf(zB * cz3, woRZ[3], boRZ))));
        float Ez = ex2f(-o_z);

        // u2 = 2*log2e*(o_x + o_h*r), r = sigmoid(o_r)
        float r  = rcpf(1.0f + Er);
        float u2 = fmaf(o_h, r, o_x);
        float Eu = ex2f(-u2);

        // h' = (Ez(1-Eu) + h(1+Eu)) / ((1+Eu)(1+Ez))
        float t2  = 1.0f + Eu;
        float num = fmaf(Ez, 1.0f - Eu, hj * t2);
        float den = t2 * (1.0f + Ez);
        hj = num * rcpf(den);

        orow[(size_t)t * HD] = hj;      // hidden_seq[b, t, j] (off-chain STG)
    }

    // h_last
    out[(size_t)NB * T_STEPS * HD + b * HD + j] = hj;
}

extern "C" void kernel_launch(void* const* d_in, const int* in_sizes, int n_in,
                              void* d_out, int out_size) {
    const float* x     = (const float*)d_in[0];
    const float* W_in  = (const float*)d_in[1];
    const float* b_in  = (const float*)d_in[2];
    const float* W_x   = (const float*)d_in[3];
    const float* b_x   = (const float*)d_in[4];
    const float* W_h   = (const float*)d_in[5];
    const float* b_h   = (const float*)d_in[6];
    const float* W_out = (const float*)d_in[7];
    const float* b_out = (const float*)d_in[8];
    const float* vqcw  = (const float*)d_in[9];
    float* out = (float*)d_out;

    const int smem_bytes = (2 * T_STEPS * 8 + 2 * 2 * 8 * 20) * sizeof(float);
    cudaFuncSetAttribute(qgru_seq, cudaFuncAttributeMaxDynamicSharedMemorySize,
                         smem_bytes);

    qgru_prepass<<<PP_WARPS / 8, 256>>>(x, W_in, b_in, W_x, b_x, vqcw);
    qgru_seq<<<NB / 2, 256, smem_bytes>>>(W_in, W_h, b_h, W_out, b_out,
                                          vqcw, out);
}

// round 16
// speedup vs baseline: 1.2059x; 1.2059x over previous
#include <cuda_runtime.h>
#include <math.h>

#define T_STEPS 1024
#define NB 128
#define FD 128
#define HD 128

// Scratch: 8 precomputed floats per (b,t):
//  [0:4) = x_t @ W_in_x^T + b_in   (x-part of y)
//  [4:8) = vqc(x_t @ W_x^T + b_x, vqc_w[2])  (fully h-independent)
__device__ float g_xpre[NB * T_STEPS * 8];

typedef unsigned long long u64;

__device__ __forceinline__ u64 pack2(float lo, float hi) {
    u64 r;
    asm("mov.b64 %0, {%1, %2};" : "=l"(r) : "f"(lo), "f"(hi));
    return r;
}
__device__ __forceinline__ void unpack2(u64 v, float& lo, float& hi) {
    asm("mov.b64 {%0, %1}, %2;" : "=f"(lo), "=f"(hi) : "l"(v));
}
__device__ __forceinline__ u64 fma2(u64 a, u64 b, u64 c) {
    u64 r;
    asm("fma.rn.f32x2 %0, %1, %2, %3;" : "=l"(r) : "l"(a), "l"(b), "l"(c));
    return r;
}
__device__ __forceinline__ u64 add2(u64 a, u64 b) {
    u64 r;
    asm("add.rn.f32x2 %0, %1, %2;" : "=l"(r) : "l"(a), "l"(b));
    return r;
}
__device__ __forceinline__ float ex2f(float x) {
    float r;
    asm("ex2.approx.f32 %0, %1;" : "=f"(r) : "f"(x));
    return r;
}
__device__ __forceinline__ float rcpf(float x) {
    float r;
    asm("rcp.approx.f32 %0, %1;" : "=f"(r) : "f"(x));
    return r;
}

// ---------------------------------------------------------------------------
// Pre-pass: TWO rows per warp-iteration. Butterfly over 16 values
// (2 rows x 8 sums) = 16 shuffles for two rows (8/row vs 13). Final layout:
// lane holds (row = bit4, sum k = bit3*4 + bit2*2 + bit1), replicated over
// bit0. One MUFU.COS serves both rows; cosine products via 2-shuffle
// pair-product trick (xor2 then xor4). 16 rows/warp in 8 double-buffered
// iterations.
// ---------------------------------------------------------------------------
#define PP_WARPS 8192

__global__ void __launch_bounds__(256) qgru_prepass(
    const float* __restrict__ x,
    const float* __restrict__ W_in, const float* __restrict__ b_in,
    const float* __restrict__ W_x,  const float* __restrict__ b_x,
    const float* __restrict__ vqc_w)
{
    const int lane = threadIdx.x & 31;
    const int gw   = (blockIdx.x * blockDim.x + threadIdx.x) >> 5;  // 0..8191

    // owned (row, sum) after the 5-round butterfly
    const int b4 = (lane >> 4) & 1;           // row select (0=A, 1=B)
    const int b3 = (lane >> 3) & 1;
    const int b2 = (lane >> 2) & 1;
    const int b1 = (lane >> 1) & 1;
    const int k  = b3 * 4 + b2 * 2 + b1;      // owned sum 0..7
    const int ci = b2 * 2 + b1;               // cosine index for k>=4 lanes

    // packed weight pairs: sum kk over x[4*lane .. 4*lane+4)
    u64 wt0[8], wt1[8];
#pragma unroll
    for (int kk = 0; kk < 8; kk++) {
        const float* row = (kk < 4) ? (W_in + kk * (HD + FD) + HD)
                                    : (W_x + (kk - 4) * FD);
        float4 wv = *reinterpret_cast<const float4*>(row + 4 * lane);
        wt0[kk] = pack2(wv.x, wv.y);
        wt1[kk] = pack2(wv.z, wv.w);
    }
    // bias for the owned sum (k>=4 folds in vqc_w[2] for the cosine arg)
    const float bias_l = (k < 4) ? b_in[k]
                                 : (b_x[k - 4] + vqc_w[8 + (k - 4)]);

    const float* xr = x + 4 * lane;   // row r lives at xr + r*FD

    // process one PAIR of rows (rowA for lanes bit4=0, rowB for bit4=1)
    auto process_pair = [&](float4 xa, float4 xb, int rowA, int rowB) {
        u64 a01 = pack2(xa.x, xa.y), a23 = pack2(xa.z, xa.w);
        u64 b01 = pack2(xb.x, xb.y), b23 = pack2(xb.z, xb.w);

        float vA[8], vB[8];
#pragma unroll
        for (int kk = 0; kk < 8; kk++) {
            u64 accA = fma2(a01, wt0[kk], fma2(a23, wt1[kk], 0ull));
            u64 accB = fma2(b01, wt0[kk], fma2(b23, wt1[kk], 0ull));
            float lo, hi;
            unpack2(accA, lo, hi); vA[kk] = lo + hi;
            unpack2(accB, lo, hi); vB[kk] = lo + hi;
        }

        // round 1 (xor16): split by row -> 8 values
        float w8[8];
#pragma unroll
        for (int i = 0; i < 8; i++) {
            float send = b4 ? vA[i] : vB[i];
            float recv = __shfl_xor_sync(0xffffffffu, send, 16);
            w8[i] = (b4 ? vB[i] : vA[i]) + recv;
        }
        // round 2 (xor8): split sums 0-3 / 4-7 -> 4 values
        float w4[4];
#pragma unroll
        for (int i = 0; i < 4; i++) {
            float send = b3 ? w8[i] : w8[4 + i];
            float recv = __shfl_xor_sync(0xffffffffu, send, 8);
            w4[i] = (b3 ? w8[4 + i] : w8[i]) + recv;
        }
        // round 3 (xor4): -> 2 values
        float w2[2];
#pragma unroll
        for (int i = 0; i < 2; i++) {
            float send = b2 ? w4[i] : w4[2 + i];
            float recv = __shfl_xor_sync(0xffffffffu, send, 4);
            w2[i] = (b2 ? w4[2 + i] : w4[i]) + recv;
        }
        // round 4 (xor2): -> 1 value
        float w1;
        {
            float send = b1 ? w2[0] : w2[1];
            float recv = __shfl_xor_sync(0xffffffffu, send, 2);
            w1 = (b1 ? w2[1] : w2[0]) + recv;
        }
        // round 5 (xor1): complete the sum (pair lanes hold halves)
        float s = w1 + __shfl_xor_sync(0xffffffffu, w1, 1);

        float val = s + bias_l;
        float cv  = __cosf(val);               // meaningful for k>=4 lanes

        // pair-product trick (serves both rows at once):
        //   cp = partner cosine (xor2), pp = cv*cp, po = other pair's pp (xor4)
        float cp = __shfl_xor_sync(0xffffffffu, cv, 2);
        float pp = cv * cp;
        float po = __shfl_xor_sync(0xffffffffu, pp, 4);

        // ci==0: c1c2c3 = cp*po; ci==1: c0c1 = pp;
        // ci==2: c0c1c2 = po*cv;  ci==3: c0c1c2c3 = po*pp
        float prod = (ci == 0) ? cp * po
                   : (ci == 1) ? pp
                   : (ci == 2) ? po * cv
                               : po * pp;

        if ((lane & 1) == 0) {
            float sval = (k < 4) ? val : prod;
            int rowg = b4 ? rowB : rowA;
            g_xpre[(size_t)rowg * 8 + k] = sval;
        }
    };

    // 16 rows/warp: 8 iterations of 2 rows, double-buffered LDG
    int rA = gw;                  // rows gw + m*PP_WARPS, m = 0..15
    float4 xa = *reinterpret_cast<const float4*>(xr + (size_t)(gw + 0 * PP_WARPS) * FD);
    float4 xb = *reinterpret_cast<const float4*>(xr + (size_t)(gw + 1 * PP_WARPS) * FD);

#pragma unroll 1
    for (int jit = 0; jit < 8; jit++) {
        float4 na, nb;
        if (jit < 7) {
            na = *reinterpret_cast<const float4*>(
                xr + (size_t)(gw + (2 * jit + 2) * PP_WARPS) * FD);
            nb = *reinterpret_cast<const float4*>(
                xr + (size_t)(gw + (2 * jit + 3) * PP_WARPS) * FD);
        }
        process_pair(xa, xb,
                     gw + (2 * jit) * PP_WARPS,
                     gw + (2 * jit + 1) * PP_WARPS);
        xa = na; xb = nb;
    }
}

// ---------------------------------------------------------------------------
// Sequential recurrence (R13/R14 version — FROZEN, proven 252.3us):
// 1 CTA per batch row, 128 threads; thread j owns h_j in a register.
//  - 8 FMUL partials, 3-round value-split butterfly
//  - 32 STS into padded psum rows (stride 20, conflict-free)
//  - barrier; each lane reads its sum's 16 partials (4x LDS.128) + add2 tree
//  - one warp-wide MUFU.COS -> 12 gate cosines via 12 direct shfl.idx
//  - ex2-folded merged-division GRU update
// ---------------------------------------------------------------------------
__global__ void __launch_bounds__(128, 1) qgru_seq(
    const float* __restrict__ W_in, const float* __restrict__ W_h,
    const float* __restrict__ b_h,
    const float* __restrict__ W_out, const float* __restrict__ b_out,
    const float* __restrict__ vqc_w,
    float* __restrict__ out)
{
    const int b    = blockIdx.x;
    const int j    = threadIdx.x;
    const int lane = j & 31;
    const int w    = j >> 5;
    const int k    = lane >> 2;   // owned sum index after 3-round butterfly
    const int q    = lane & 3;    // partial index this lane holds

    __shared__ __align__(16) float xs[T_STEPS * 8];   // 32 KB staged xpre row
    __shared__ __align__(16) float psum[2][8 * 20];   // padded: row k at k*20

    // ---- stage this row's xpre into smem
    {
        const float4* src = reinterpret_cast<const float4*>(
            g_xpre + (size_t)b * T_STEPS * 8);
        float4* dst = reinterpret_cast<float4*>(xs);
        float4 tmp[16];
#pragma unroll
        for (int i = 0; i < 16; i++) tmp[i] = src[j + 128 * i];
#pragma unroll
        for (int i = 0; i < 16; i++) dst[j + 128 * i] = tmp[i];
    }

    // ---- dot weights: wk[kk] = row_kk[j]  (thread j's h column)
    float wk[8];
#pragma unroll
    for (int kk = 0; kk < 8; kk++) {
        const float* row = (kk < 4) ? (W_in + kk * (HD + FD))
                                    : (W_h + (kk - 4) * HD);
        wk[kk] = row[j];
    }

    // W_out prescaled: RZ by log2e (exp(-o)), HX by 2*log2e (exp(-2u))
    const float L2E = 1.4426950408889634f;
    float woRZ[4], woHX[4];
#pragma unroll
    for (int kk = 0; kk < 4; kk++) {
        float wv = W_out[j * 4 + kk];
        woRZ[kk] = wv * L2E;
        woHX[kk] = wv * (2.0f * L2E);
    }
    const float bof  = b_out[j];
    const float boRZ = bof * L2E;
    const float boHX = bof * (2.0f * L2E);

    // ---- cosine role (loop-invariant): quad k, member q
    float cadd = 0.0f;
    if (k < 4) {
        if (q == 0)      cadd = vqc_w[k];
        else if (q == 1) cadd = vqc_w[4 + k];
    } else if (q == 0) {
        cadd = vqc_w[12 + (k - 4)] + b_h[k - 4];
    }
    const bool use_p = (k < 4);

    const int hi = (lane >> 4) & 1;
    const int h3 = (lane >> 3) & 1;
    const int h2 = (lane >> 2) & 1;

    float hj = 0.0f;                 // h_j lives here; never leaves registers

    // c_last = zeros
    out[(size_t)NB * T_STEPS * HD + (size_t)NB * HD + b * HD + j] = 0.0f;

    float* __restrict__ orow = out + (size_t)b * T_STEPS * HD + j;
    const int pslot = k * 20 + w * 4 + q;   // this lane's psum store index

    __syncthreads();   // xs staged

#pragma unroll 1
    for (int t = 0; t < T_STEPS; t++) {
        // ---- pre-barrier: warp-partial dots over this warp's own h slice
        float v[8];
#pragma unroll
        for (int kk = 0; kk < 8; kk++) v[kk] = wk[kk] * hj;

        // 3-round value-splitting butterfly: lane ends with one partial
        // (sum k=lane>>2, over the 8 lanes sharing lane&3)
        float u4_0, u4_1, u4_2, u4_3;
        {
            float s0 = hi ? v[0] : v[4];
            float s1 = hi ? v[1] : v[5];
            float s2 = hi ? v[2] : v[6];
            float s3 = hi ? v[3] : v[7];
            float r0 = __shfl_xor_sync(0xffffffffu, s0, 16);
            float r1 = __shfl_xor_sync(0xffffffffu, s1, 16);
            float r2 = __shfl_xor_sync(0xffffffffu, s2, 16);
            float r3 = __shfl_xor_sync(0xffffffffu, s3, 16);
            u4_0 = (hi ? v[4] : v[0]) + r0;
            u4_1 = (hi ? v[5] : v[1]) + r1;
            u4_2 = (hi ? v[6] : v[2]) + r2;
            u4_3 = (hi ? v[7] : v[3]) + r3;
        }
        float u2_0, u2_1;
        {
            float s0 = h3 ? u4_0 : u4_2;
            float s1 = h3 ? u4_1 : u4_3;
            float r0 = __shfl_xor_sync(0xffffffffu, s0, 8);
            float r1 = __shfl_xor_sync(0xffffffffu, s1, 8);
            u2_0 = (h3 ? u4_2 : u4_0) + r0;
            u2_1 = (h3 ? u4_3 : u4_1) + r1;
        }
        float s;
        {
            float s0 = h2 ? u2_0 : u2_1;
            float r0 = __shfl_xor_sync(0xffffffffu, s0, 4);
            s = (h2 ? u2_1 : u2_0) + r0;
        }

        psum[t & 1][pslot] = s;      // all 32 lanes store (conflict-free)

        // psum-independent work overlapping the barrier region
        float4 P1 = *reinterpret_cast<const float4*>(xs + t * 8 + 4);
        float pc  = xs[t * 8 + (k & 3)];
        float o_x = fmaf(P1.x, woHX[0],
                    fmaf(P1.y, woHX[1], fmaf(P1.z, woHX[2],
                    fmaf(P1.w, woHX[3], boHX))));

        __syncthreads();

        // ---- post-barrier: total for owned sum k (16 partials, add2 tree)
        const float* prow = psum[t & 1] + k * 20;
        ulonglong2 A = *reinterpret_cast<const ulonglong2*>(prow + 0);
        ulonglong2 B = *reinterpret_cast<const ulonglong2*>(prow + 4);
        ulonglong2 C = *reinterpret_cast<const ulonglong2*>(prow + 8);
        ulonglong2 D = *reinterpret_cast<const ulonglong2*>(prow + 12);
        u64 e0 = add2(A.x, A.y);
        u64 e1 = add2(B.x, B.y);
        u64 e2 = add2(C.x, C.y);
        u64 e3 = add2(D.x, D.y);
        e0 = add2(e0, e1);
        e2 = add2(e2, e3);
        e0 = add2(e0, e2);
        float tlo, thi;
        unpack2(e0, tlo, thi);
        float tot = tlo + thi;

        // one warp-wide cosine; 12 direct shfl.idx broadcasts (no smem)
        float arg = tot + cadd + (use_p ? pc : 0.0f);
        float cv  = __cosf(arg);

        float cr0 = __shfl_sync(0xffffffffu, cv, 0);
        float cr1 = __shfl_sync(0xffffffffu, cv, 4);
        float cr2 = __shfl_sync(0xffffffffu, cv, 8);
        float cr3 = __shfl_sync(0xffffffffu, cv, 12);
        float cz0 = __shfl_sync(0xffffffffu, cv, 1);
        float cz1 = __shfl_sync(0xffffffffu, cv, 5);
        float cz2 = __shfl_sync(0xffffffffu, cv, 9);
        float cz3 = __shfl_sync(0xffffffffu, cv, 13);
        float ch0 = __shfl_sync(0xffffffffu, cv, 16);
        float ch1 = __shfl_sync(0xffffffffu, cv, 20);
        float ch2 = __shfl_sync(0xffffffffu, cv, 24);
        float ch3 = __shfl_sync(0xffffffffu, cv, 28);

        // z-expectations after CNOT ring: (C1C2C3, C0C1, C0C1C2, C0C1C2C3)
        float rm = cr1 * cr2;
        float rA = cr0 * cr1, rB = cr0 * rm;
        float o_r = fmaf(rm * cr3, woRZ[0],
                    fmaf(rA, woRZ[1], fmaf(rB, woRZ[2],
                    fmaf(rB * cr3, woRZ[3], boRZ))));
        float Er = ex2f(-o_r);

        float hm = ch1 * ch2;
        float hA = ch0 * ch1, hB = ch0 * hm;
        float o_h = fmaf(hm * ch3, woHX[0],
                    fmaf(hA, woHX[1], fmaf(hB, woHX[2],
                    fmaf(hB * ch3, woHX[3], boHX))));

        float zm = cz1 * cz2;
        float zA = cz0 * cz1, zB = cz0 * zm;
        float o_z = fmaf(zm * cz3, woRZ[0],
                    fmaf(zA, woRZ[1], fmaf(zB, woRZ[2],
                    fmaf(zB * cz3, woRZ[3], boRZ))));
        float Ez = ex2f(-o_z);

        // u2 = 2*log2e*(o_x + o_h*r), r = sigmoid(o_r)
        float r  = rcpf(1.0f + Er);
        float u2 = fmaf(o_h, r, o_x);
        float Eu = ex2f(-u2);

        // h' = (Ez(1-Eu) + h(1+Eu)) / ((1+Eu)(1+Ez))
        float t2  = 1.0f + Eu;
        float num = fmaf(Ez, 1.0f - Eu, hj * t2);
        float den = t2 * (1.0f + Ez);
        hj = num * rcpf(den);

        orow[(size_t)t * HD] = hj;      // hidden_seq[b, t, j] (off-chain STG)
    }

    // h_last
    out[(size_t)NB * T_STEPS * HD + b * HD + j] = hj;
}

extern "C" void kernel_launch(void* const* d_in, const int* in_sizes, int n_in,
                              void* d_out, int out_size) {
    const float* x     = (const float*)d_in[0];
    const float* W_in  = (const float*)d_in[1];
    const float* b_in  = (const float*)d_in[2];
    const float* W_x   = (const float*)d_in[3];
    const float* b_x   = (const float*)d_in[4];
    const float* W_h   = (const float*)d_in[5];
    const float* b_h   = (const float*)d_in[6];
    const float* W_out = (const float*)d_in[7];
    const float* b_out = (const float*)d_in[8];
    const float* vqcw  = (const float*)d_in[9];
    float* out = (float*)d_out;

    qgru_prepass<<<PP_WARPS / 8, 256>>>(x, W_in, b_in, W_x, b_x, vqcw);
    qgru_seq<<<NB, HD>>>(W_in, W_h, b_h, W_out, b_out, vqcw, out);
}